// round 9
// baseline (speedup 1.0000x reference)
#include <cuda_runtime.h>
#include <cstdint>

// KNN entropy estimator — cluster/DSMEM form, constant-folded tail.
//   mc_c = (k+1)-th largest of column c
//   sum_i eps = 2*S_c - N*mc - corr(top6) - N*max(mc,0)   (clippers are in the top-6)
//   H = C(k) + (1/N) * sum_c colv_c,  C(k) = gamma - H_{k-1} + digamma(16) + 15/k
//
// One cluster of 8 CTAs x 512 thr. Ranks 1..7 push (top6,S) records into rank
// 0's SMEM (st.shared::cluster.v4 + release arrive); rank 0 keeps its own slab
// in registers, try_waits once, merges 8 records/column, finalizes H.
// Cluster barrier is split: everyone arrives after mbarrier init; only
// publishers wait (just before the push) -> rank 0's path never stalls on skew.

#define NN   2048
#define DD   16
#define NCTA 8
#define TPB  512
#define CST  260             // padded column stride (256 rows + 4 floats)
#define RSL  132             // record slab stride in floats (528 B)
#define NARR (7 * 16)        // arrivals: ranks 1..7, one per warp
#define NEGF (-1e30f)

// C(k) = gamma - H_{k-1} + digamma(16) + 15/k, k = 1..6 (double-precomputed).
__device__ const float C_TAB[6] = {
    18.31822899f,  // k=1
     9.81822899f,  // k=2
     6.81822899f,  // k=3
     5.23489566f,  // k=4
     4.23489566f,  // k=5
     3.53489566f   // k=6
};

__device__ __forceinline__ void ce(float& a, float& b) {   // descending comparator
    float h = fmaxf(a, b), l = fminf(a, b); a = h; b = l;
}

// Optimal 6-element sorting network (12 CE, depth 5), descending.
__device__ __forceinline__ void sort6(float t[6]) {
    ce(t[0],t[5]); ce(t[1],t[3]); ce(t[2],t[4]);
    ce(t[1],t[2]); ce(t[3],t[4]);
    ce(t[0],t[3]); ce(t[2],t[5]);
    ce(t[0],t[1]); ce(t[2],t[3]); ce(t[4],t[5]);
    ce(t[1],t[2]); ce(t[3],t[4]);
}

// Merge two descending 6-lists, keep top-6 (bitonic split + sort6).
__device__ __forceinline__ void merge6(float t[6], const float o[6]) {
    t[0]=fmaxf(t[0],o[5]); t[1]=fmaxf(t[1],o[4]); t[2]=fmaxf(t[2],o[3]);
    t[3]=fmaxf(t[3],o[2]); t[4]=fmaxf(t[4],o[1]); t[5]=fmaxf(t[5],o[0]);
    sort6(t);
}

template<int FIRST_OFF>
__device__ __forceinline__ void shfl_merge6(float t[6]) {
#pragma unroll
    for (int off = FIRST_OFF; off >= 1; off >>= 1) {
        float o[6];
#pragma unroll
        for (int e = 0; e < 6; e++)
            o[e] = __shfl_down_sync(0xffffffffu, t[e], off);
        merge6(t, o);
    }
}

__device__ __forceinline__ uint32_t smem_u32(const void* p) {
    uint32_t a;
    asm("{ .reg .u64 t; cvta.to.shared.u64 t, %1; cvt.u32.u64 %0, t; }"
        : "=r"(a) : "l"(p));
    return a;
}

extern "C" __global__ void __launch_bounds__(TPB, 1)
__cluster_dims__(NCTA, 1, 1)
knn_entropy_kernel(const float* __restrict__ x,
                   const int* __restrict__ kptr,
                   float* __restrict__ out) {
    __shared__ __align__(16) float sxt[DD * CST];    // transposed slab
    __shared__ __align__(16) float recs[NCTA * RSL]; // rank0: incoming records
    __shared__ __align__(8)  unsigned long long mbar;
    __shared__ float colv[DD];

    const int tid  = threadIdx.x;
    const int w    = tid >> 5;
    const int lane = tid & 31;
    uint32_t rank;
    asm("mov.u32 %0, %%cluster_ctarank;" : "=r"(rank));

    const int k = __ldg(kptr);

    // ---- Issue slab loads (rows 256*rank .. +255), 2 float4/thread ----
    const float4* x4 = (const float4*)x;
    float4 f0 = x4[rank * 1024 + tid];
    float4 f1 = x4[rank * 1024 + tid + 512];

    // ---- mbarrier init + cluster ARRIVE (wait deferred to publishers) ----
    const uint32_t mb = smem_u32(&mbar);
    if (rank == 0 && tid == 0) {
        asm volatile("mbarrier.init.shared.b64 [%0], %1;" :: "r"(mb), "r"(NARR) : "memory");
        asm volatile("fence.mbarrier_init.release.cluster;" ::: "memory");
    }
    asm volatile("barrier.cluster.arrive.aligned;" ::: "memory");

    // ---- Transpose into SMEM (8 STS, 2-way conflicts) ----
    {
        int p = tid, row = p >> 2, c0 = (p & 3) << 2;
        sxt[(c0+0)*CST + row] = f0.x; sxt[(c0+1)*CST + row] = f0.y;
        sxt[(c0+2)*CST + row] = f0.z; sxt[(c0+3)*CST + row] = f0.w;
        p = tid + 512; row = p >> 2; c0 = (p & 3) << 2;
        sxt[(c0+0)*CST + row] = f1.x; sxt[(c0+1)*CST + row] = f1.y;
        sxt[(c0+2)*CST + row] = f1.z; sxt[(c0+3)*CST + row] = f1.w;
    }
    __syncthreads();

    // ---- Warp w: slab top-6 + sum of column w (8 values/lane) ----
    const float4* colq = (const float4*)(sxt + w * CST);
    float4 ga = colq[lane];
    float4 gb = colq[lane + 32];

    float s = ((ga.x + ga.y) + (ga.z + ga.w)) + ((gb.x + gb.y) + (gb.z + gb.w));
    ce(ga.x, ga.z); ce(ga.y, ga.w); ce(ga.x, ga.y); ce(ga.z, ga.w); ce(ga.y, ga.z);
    ce(gb.x, gb.z); ce(gb.y, gb.w); ce(gb.x, gb.y); ce(gb.z, gb.w); ce(gb.y, gb.z);
    float t[6] = { ga.x, ga.y, ga.z, ga.w, NEGF, NEGF };
    {
        float o[6] = { gb.x, gb.y, gb.z, gb.w, NEGF, NEGF };
        merge6(t, o);
    }
    shfl_merge6<16>(t);
#pragma unroll
    for (int off = 16; off >= 1; off >>= 1)
        s += __shfl_down_sync(0xffffffffu, s, off);
    // lane 0 holds this slab's (top6, S) for column w

    if (rank != 0) {
        // init-visibility needed only now; skew absorbed into our compute
        asm volatile("barrier.cluster.wait.aligned;" ::: "memory");
        if (lane == 0) {    // push record into rank0's SMEM, then release-arrive
            uint32_t loc = smem_u32(&recs[rank * RSL + w * 8]);
            uint32_t dst, rmb;
            asm("mapa.shared::cluster.u32 %0, %1, 0;" : "=r"(dst) : "r"(loc));
            asm("mapa.shared::cluster.u32 %0, %1, 0;" : "=r"(rmb) : "r"(mb));
            asm volatile("st.shared::cluster.v4.f32 [%0], {%1,%2,%3,%4};"
                         :: "r"(dst), "f"(t[0]), "f"(t[1]), "f"(t[2]), "f"(t[3]) : "memory");
            asm volatile("st.shared::cluster.v4.f32 [%0], {%1,%2,%3,%4};"
                         :: "r"(dst + 16), "f"(t[4]), "f"(t[5]), "f"(s), "f"(0.0f) : "memory");
            asm volatile("mbarrier.arrive.release.cluster.shared::cluster.b64 _, [%0];"
                         :: "r"(rmb) : "memory");
        }
        return;
    }

    // ================= rank 0: wait once, then combine =================
    {
        uint32_t done;
        asm volatile(
            "{\n\t"
            ".reg .pred p;\n\t"
            "WL_%=:\n\t"
            "mbarrier.try_wait.parity.acquire.cluster.shared::cta.b64 p, [%1], %2, 0x989680;\n\t"
            "@p bra WD_%=;\n\t"
            "bra WL_%=;\n\t"
            "WD_%=:\n\t"
            "mov.u32 %0, 1;\n\t"
            "}"
            : "=r"(done) : "r"(mb), "r"(0) : "memory");
        (void)done;
    }

    // Warp w merges its own record (lane 0, in regs) + 7 pushed records.
    float t2[6];
    float s2;
    if (lane == 0) {
#pragma unroll
        for (int e = 0; e < 6; e++) t2[e] = t[e];
        s2 = s;
    } else if (lane < NCTA) {          // conflict-free: bank = (4*lane + 8w) % 32
        const float4* r4 = (const float4*)&recs[lane * RSL + w * 8];
        float4 ra = r4[0], rb = r4[1];
        t2[0]=ra.x; t2[1]=ra.y; t2[2]=ra.z; t2[3]=ra.w;
        t2[4]=rb.x; t2[5]=rb.y; s2 = rb.z;
    } else {
#pragma unroll
        for (int e = 0; e < 6; e++) t2[e] = NEGF;
        s2 = 0.0f;
    }

    shfl_merge6<4>(t2);
#pragma unroll
    for (int off = 4; off >= 1; off >>= 1)
        s2 += __shfl_down_sync(0xffffffffu, s2, off);

    if (lane == 0) {
        const int kk = k < 1 ? 1 : (k > 5 ? 5 : k);   // mc index = kk within top-6
        float mc = t2[kk];
        const float tau = 0.5f * (1.0f + mc);
        float corr = 0.0f;
#pragma unroll
        for (int e = 0; e < 6; e++)
            if (t2[e] > tau) corr += 2.0f * t2[e] - mc - 1.0f;
        colv[w] = 2.0f * s2 - (float)NN * mc - corr - (float)NN * fmaxf(mc, 0.0f);
    }
    __syncthreads();

    if (w == 0) {
        float a = (lane < DD) ? colv[lane] : 0.0f;
#pragma unroll
        for (int off = 8; off >= 1; off >>= 1)
            a += __shfl_down_sync(0xffffffffu, a, off);
        if (lane == 0) {
            const int kc = k < 1 ? 1 : (k > 6 ? 6 : k);
            out[0] = C_TAB[kc - 1] + a * (1.0f / (float)NN);
        }
    }
}

extern "C" void kernel_launch(void* const* d_in, const int* in_sizes, int n_in,
                              void* d_out, int out_size) {
    // metadata order: x [N*D f32], k [1 i32] — pick by size to be robust.
    int xi = 0, ki = 1;
    if (n_in >= 2 && in_sizes[0] == 1) { xi = 1; ki = 0; }
    const float* x    = (const float*)d_in[xi];
    const int*   kptr = (const int*)d_in[ki];
    float*       out  = (float*)d_out;

    knn_entropy_kernel<<<NCTA, TPB>>>(x, kptr, out);
}

// round 10
// speedup vs baseline: 1.0613x; 1.0613x over previous
#include <cuda_runtime.h>
#include <cstdint>

// KNN entropy estimator — cluster/DSMEM form (R8 handshake + immediate-constant tail).
//   mc_c = (k+1)-th largest of column c
//   sum_i eps = 2*S_c - N*mc - corr(top6) - N*max(mc,0)   (clippers are in the top-6)
//   H = C(k) + (1/N) * sum_c colv_c,  C(k) = gamma - H_{k-1} + digamma(16) + 15/k
//
// One cluster of 8 CTAs x 512 thr. cluster.sync sits fully inside the DRAM
// load shadow (R8 placement — moving it later exposed it, R9 post-mortem).
// Ranks 1..7 push (top6,S) records into rank 0's SMEM via st.shared::cluster.v4
// + release arrive; rank 0 keeps its own slab in registers, try_waits once,
// merges 8 records/column, finalizes H with compile-time C(k) selected into a
// register (no memory access on the tail).

#define NN   2048
#define DD   16
#define NCTA 8
#define TPB  512
#define CST  260             // padded column stride (256 rows + 4 floats)
#define RSL  132             // record slab stride in floats (528 B)
#define NARR (7 * 16)        // arrivals: ranks 1..7, one per warp
#define NEGF (-1e30f)

__device__ __forceinline__ void ce(float& a, float& b) {   // descending comparator
    float h = fmaxf(a, b), l = fminf(a, b); a = h; b = l;
}

// Optimal 6-element sorting network (12 CE, depth 5), descending.
__device__ __forceinline__ void sort6(float t[6]) {
    ce(t[0],t[5]); ce(t[1],t[3]); ce(t[2],t[4]);
    ce(t[1],t[2]); ce(t[3],t[4]);
    ce(t[0],t[3]); ce(t[2],t[5]);
    ce(t[0],t[1]); ce(t[2],t[3]); ce(t[4],t[5]);
    ce(t[1],t[2]); ce(t[3],t[4]);
}

// Merge two descending 6-lists, keep top-6 (bitonic split + sort6).
__device__ __forceinline__ void merge6(float t[6], const float o[6]) {
    t[0]=fmaxf(t[0],o[5]); t[1]=fmaxf(t[1],o[4]); t[2]=fmaxf(t[2],o[3]);
    t[3]=fmaxf(t[3],o[2]); t[4]=fmaxf(t[4],o[1]); t[5]=fmaxf(t[5],o[0]);
    sort6(t);
}

template<int FIRST_OFF>
__device__ __forceinline__ void shfl_merge6(float t[6]) {
#pragma unroll
    for (int off = FIRST_OFF; off >= 1; off >>= 1) {
        float o[6];
#pragma unroll
        for (int e = 0; e < 6; e++)
            o[e] = __shfl_down_sync(0xffffffffu, t[e], off);
        merge6(t, o);
    }
}

__device__ __forceinline__ uint32_t smem_u32(const void* p) {
    uint32_t a;
    asm("{ .reg .u64 t; cvta.to.shared.u64 t, %1; cvt.u32.u64 %0, t; }"
        : "=r"(a) : "l"(p));
    return a;
}

extern "C" __global__ void __launch_bounds__(TPB, 1)
__cluster_dims__(NCTA, 1, 1)
knn_entropy_kernel(const float* __restrict__ x,
                   const int* __restrict__ kptr,
                   float* __restrict__ out) {
    __shared__ __align__(16) float sxt[DD * CST];    // transposed slab
    __shared__ __align__(16) float recs[NCTA * RSL]; // rank0: incoming records
    __shared__ __align__(8)  unsigned long long mbar;
    __shared__ float colv[DD];

    const int tid  = threadIdx.x;
    const int w    = tid >> 5;
    const int lane = tid & 31;
    uint32_t rank;
    asm("mov.u32 %0, %%cluster_ctarank;" : "=r"(rank));

    const int k = __ldg(kptr);

    // ---- Issue slab loads (rows 256*rank .. +255), 2 float4/thread ----
    const float4* x4 = (const float4*)x;
    float4 f0 = x4[rank * 1024 + tid];
    float4 f1 = x4[rank * 1024 + tid + 512];

    // ---- mbarrier init + full cluster.sync UNDER THE LOAD SHADOW (R8) ----
    const uint32_t mb = smem_u32(&mbar);
    if (rank == 0 && tid == 0) {
        asm volatile("mbarrier.init.shared.b64 [%0], %1;" :: "r"(mb), "r"(NARR) : "memory");
        asm volatile("fence.mbarrier_init.release.cluster;" ::: "memory");
    }
    asm volatile("barrier.cluster.arrive.aligned;" ::: "memory");
    asm volatile("barrier.cluster.wait.aligned;"  ::: "memory");

    // ---- Transpose into SMEM (8 STS, 2-way conflicts) ----
    {
        int p = tid, row = p >> 2, c0 = (p & 3) << 2;
        sxt[(c0+0)*CST + row] = f0.x; sxt[(c0+1)*CST + row] = f0.y;
        sxt[(c0+2)*CST + row] = f0.z; sxt[(c0+3)*CST + row] = f0.w;
        p = tid + 512; row = p >> 2; c0 = (p & 3) << 2;
        sxt[(c0+0)*CST + row] = f1.x; sxt[(c0+1)*CST + row] = f1.y;
        sxt[(c0+2)*CST + row] = f1.z; sxt[(c0+3)*CST + row] = f1.w;
    }
    __syncthreads();

    // ---- Warp w: slab top-6 + sum of column w (8 values/lane) ----
    const float4* colq = (const float4*)(sxt + w * CST);
    float4 ga = colq[lane];
    float4 gb = colq[lane + 32];

    float s = ((ga.x + ga.y) + (ga.z + ga.w)) + ((gb.x + gb.y) + (gb.z + gb.w));
    ce(ga.x, ga.z); ce(ga.y, ga.w); ce(ga.x, ga.y); ce(ga.z, ga.w); ce(ga.y, ga.z);
    ce(gb.x, gb.z); ce(gb.y, gb.w); ce(gb.x, gb.y); ce(gb.z, gb.w); ce(gb.y, gb.z);
    float t[6] = { ga.x, ga.y, ga.z, ga.w, NEGF, NEGF };
    {
        float o[6] = { gb.x, gb.y, gb.z, gb.w, NEGF, NEGF };
        merge6(t, o);
    }
    shfl_merge6<16>(t);
#pragma unroll
    for (int off = 16; off >= 1; off >>= 1)
        s += __shfl_down_sync(0xffffffffu, s, off);
    // lane 0 holds this slab's (top6, S) for column w

    if (rank != 0) {
        if (lane == 0) {    // push record into rank0's SMEM, then release-arrive
            uint32_t loc = smem_u32(&recs[rank * RSL + w * 8]);
            uint32_t dst, rmb;
            asm("mapa.shared::cluster.u32 %0, %1, 0;" : "=r"(dst) : "r"(loc));
            asm("mapa.shared::cluster.u32 %0, %1, 0;" : "=r"(rmb) : "r"(mb));
            asm volatile("st.shared::cluster.v4.f32 [%0], {%1,%2,%3,%4};"
                         :: "r"(dst), "f"(t[0]), "f"(t[1]), "f"(t[2]), "f"(t[3]) : "memory");
            asm volatile("st.shared::cluster.v4.f32 [%0], {%1,%2,%3,%4};"
                         :: "r"(dst + 16), "f"(t[4]), "f"(t[5]), "f"(s), "f"(0.0f) : "memory");
            asm volatile("mbarrier.arrive.release.cluster.shared::cluster.b64 _, [%0];"
                         :: "r"(rmb) : "memory");
        }
        return;
    }

    // ================= rank 0: wait once, then combine =================
    {
        uint32_t done;
        asm volatile(
            "{\n\t"
            ".reg .pred p;\n\t"
            "WL_%=:\n\t"
            "mbarrier.try_wait.parity.acquire.cluster.shared::cta.b64 p, [%1], %2, 0x989680;\n\t"
            "@p bra WD_%=;\n\t"
            "bra WL_%=;\n\t"
            "WD_%=:\n\t"
            "mov.u32 %0, 1;\n\t"
            "}"
            : "=r"(done) : "r"(mb), "r"(0) : "memory");
        (void)done;
    }

    // Warp w merges its own record (lane 0, in regs) + 7 pushed records.
    float t2[6];
    float s2;
    if (lane == 0) {
#pragma unroll
        for (int e = 0; e < 6; e++) t2[e] = t[e];
        s2 = s;
    } else if (lane < NCTA) {          // conflict-free: bank = (4*lane + 8w) % 32
        const float4* r4 = (const float4*)&recs[lane * RSL + w * 8];
        float4 ra = r4[0], rb = r4[1];
        t2[0]=ra.x; t2[1]=ra.y; t2[2]=ra.z; t2[3]=ra.w;
        t2[4]=rb.x; t2[5]=rb.y; s2 = rb.z;
    } else {
#pragma unroll
        for (int e = 0; e < 6; e++) t2[e] = NEGF;
        s2 = 0.0f;
    }

    shfl_merge6<4>(t2);
#pragma unroll
    for (int off = 4; off >= 1; off >>= 1)
        s2 += __shfl_down_sync(0xffffffffu, s2, off);

    if (lane == 0) {
        const int kk = k < 1 ? 1 : (k > 5 ? 5 : k);   // mc index = kk within top-6
        float mc = t2[kk];
        const float tau = 0.5f * (1.0f + mc);
        float corr = 0.0f;
#pragma unroll
        for (int e = 0; e < 6; e++)
            if (t2[e] > tau) corr += 2.0f * t2[e] - mc - 1.0f;
        colv[w] = 2.0f * s2 - (float)NN * mc - corr - (float)NN * fmaxf(mc, 0.0f);
    }
    __syncthreads();

    if (w == 0) {
        float a = (lane < DD) ? colv[lane] : 0.0f;
#pragma unroll
        for (int off = 8; off >= 1; off >>= 1)
            a += __shfl_down_sync(0xffffffffu, a, off);
        if (lane == 0) {
            // C(k) = gamma - H_{k-1} + digamma(16) + 15/k, double-precomputed,
            // selected into a register (no memory access).
            float C = (k <= 1) ? 18.31822899f :
                      (k == 2) ?  9.81822899f :
                      (k == 3) ?  6.81822899f :
                      (k == 4) ?  5.23489566f :
                      (k == 5) ?  4.23489566f :
                                  3.53489566f;        // k >= 6
            out[0] = C + a * (1.0f / (float)NN);
        }
    }
}

extern "C" void kernel_launch(void* const* d_in, const int* in_sizes, int n_in,
                              void* d_out, int out_size) {
    // metadata order: x [N*D f32], k [1 i32] — pick by size to be robust.
    int xi = 0, ki = 1;
    if (n_in >= 2 && in_sizes[0] == 1) { xi = 1; ki = 0; }
    const float* x    = (const float*)d_in[xi];
    const int*   kptr = (const int*)d_in[ki];
    float*       out  = (float*)d_out;

    knn_entropy_kernel<<<NCTA, TPB>>>(x, kptr, out);
}